// round 1
// baseline (speedup 1.0000x reference)
#include <cuda_runtime.h>
#include <math.h>

#define N_NODES 25000
#define N_EDGES 400000
#define HDIM 128

// ---- device scratch (no allocations allowed) ----
__device__ float g_x[N_NODES * 384];      // per-node interaction MLP output
__device__ int   g_cnt[N_NODES];
__device__ int   g_off[N_NODES + 1];
__device__ int   g_cur[N_NODES];
__device__ int   g_eidx[N_EDGES];

__device__ __forceinline__ float silu_f(float x) {
    return x / (1.0f + __expf(-x));
}
__device__ __forceinline__ float clip100(float x) {
    return fminf(fmaxf(x, -100.0f), 100.0f);
}
__device__ __forceinline__ float4 f4z() { float4 r; r.x=r.y=r.z=r.w=0.f; return r; }
__device__ __forceinline__ float4 f4fma(float a, float4 b, float4 c) {
    c.x = fmaf(a, b.x, c.x); c.y = fmaf(a, b.y, c.y);
    c.z = fmaf(a, b.z, c.z); c.w = fmaf(a, b.w, c.w); return c;
}
__device__ __forceinline__ float4 f4mul(float4 a, float4 b) {
    float4 r; r.x=a.x*b.x; r.y=a.y*b.y; r.z=a.z*b.z; r.w=a.w*b.w; return r;
}
__device__ __forceinline__ float4 f4fma4(float4 a, float4 b, float4 c) {
    c.x = fmaf(a.x, b.x, c.x); c.y = fmaf(a.y, b.y, c.y);
    c.z = fmaf(a.z, b.z, c.z); c.w = fmaf(a.w, b.w, c.w); return c;
}
__device__ __forceinline__ float4 f4add(float4 a, float4 b) {
    float4 r; r.x=a.x+b.x; r.y=a.y+b.y; r.z=a.z+b.z; r.w=a.w+b.w; return r;
}
__device__ __forceinline__ float4 f4clip(float4 a) {
    float4 r; r.x=clip100(a.x); r.y=clip100(a.y); r.z=clip100(a.z); r.w=clip100(a.w); return r;
}
__device__ __forceinline__ float4 f4silu(float4 a) {
    float4 r; r.x=silu_f(a.x); r.y=silu_f(a.y); r.z=silu_f(a.z); r.w=silu_f(a.w); return r;
}

// ============================================================
// Kernel 1: x = silu(s @ Wi1 + bi1) @ Wi2 + bi2   (one warp per node)
// ============================================================
__global__ void k_node_mlp(const float* __restrict__ s,
                           const float* __restrict__ Wi1, const float* __restrict__ bi1,
                           const float* __restrict__ Wi2, const float* __restrict__ bi2) {
    int gw   = (blockIdx.x * blockDim.x + threadIdx.x) >> 5;
    int lane = threadIdx.x & 31;
    int wl   = threadIdx.x >> 5;
    __shared__ float sm[8][256];   // [0:128) s row, [128:256) hidden
    if (gw >= N_NODES) return;

    float* ss = sm[wl];
    float* sh = sm[wl] + 128;
    ((float4*)ss)[lane] = ((const float4*)(s + gw * HDIM))[lane];
    __syncwarp();

    float4 h4 = f4z();
#pragma unroll 8
    for (int k = 0; k < 128; k++) {
        float sk = ss[k];
        float4 w = *(const float4*)(Wi1 + k * 128 + lane * 4);
        h4 = f4fma(sk, w, h4);
    }
    h4 = f4add(h4, ((const float4*)bi1)[lane]);
    h4 = f4silu(h4);
    ((float4*)sh)[lane] = h4;
    __syncwarp();

#pragma unroll
    for (int c = 0; c < 3; c++) {
        float4 o = f4z();
#pragma unroll 8
        for (int k = 0; k < 128; k++) {
            float hk = sh[k];
            float4 w = *(const float4*)(Wi2 + k * 384 + c * 128 + lane * 4);
            o = f4fma(hk, w, o);
        }
        o = f4add(o, ((const float4*)(bi2 + c * 128))[lane]);
        ((float4*)(g_x + gw * 384 + c * 128))[lane] = o;
    }
}

// ============================================================
// CSR build by sender
// ============================================================
__global__ void k_zero_cnt() {
    int i = blockIdx.x * blockDim.x + threadIdx.x;
    if (i < N_NODES) g_cnt[i] = 0;
}
__global__ void k_count(const int* __restrict__ senders) {
    int e = blockIdx.x * blockDim.x + threadIdx.x;
    if (e < N_EDGES) atomicAdd(&g_cnt[senders[e]], 1);
}
__global__ void k_scan() {
    __shared__ int sm[1024];
    int t = threadIdx.x;
    const int CH = (N_NODES + 1023) / 1024;   // 25
    int base = t * CH;
    int sum = 0;
    for (int i = 0; i < CH; i++) {
        int idx = base + i;
        if (idx < N_NODES) sum += g_cnt[idx];
    }
    sm[t] = sum;
    __syncthreads();
    for (int off = 1; off < 1024; off <<= 1) {
        int v = (t >= off) ? sm[t - off] : 0;
        __syncthreads();
        sm[t] += v;
        __syncthreads();
    }
    int run = (t == 0) ? 0 : sm[t - 1];
    for (int i = 0; i < CH; i++) {
        int idx = base + i;
        if (idx < N_NODES) {
            g_off[idx] = run;
            g_cur[idx] = run;
            run += g_cnt[idx];
        }
    }
    if (t == 1023) g_off[N_NODES] = sm[1023];
}
__global__ void k_fill(const int* __restrict__ senders) {
    int e = blockIdx.x * blockDim.x + threadIdx.x;
    if (e < N_EDGES) {
        int p = atomicAdd(&g_cur[senders[e]], 1);
        g_eidx[p] = e;
    }
}

// ============================================================
// Kernel 2: message gather-reduce, one warp per node (sender)
//   out_s = s + clip(sum ds_e), out_v = v + clip(sum dv_e)
// ============================================================
__global__ void k_message(const float* __restrict__ s, const float* __restrict__ v,
                          const float* __restrict__ dir_ij, const float* __restrict__ Wij,
                          const int* __restrict__ receivers,
                          float* __restrict__ out_s, float* __restrict__ out_v) {
    int node = (blockIdx.x * blockDim.x + threadIdx.x) >> 5;
    int lane = threadIdx.x & 31;
    if (node >= N_NODES) return;

    float4 ds  = f4z();
    float4 dv0 = f4z(), dv1 = f4z(), dv2 = f4z();

    int beg = g_off[node], end = g_off[node + 1];
    for (int i = beg; i < end; i++) {
        int e = g_eidx[i];
        int r = receivers[e];
        float d0 = dir_ij[e * 3 + 0];
        float d1 = dir_ij[e * 3 + 1];
        float d2 = dir_ij[e * 3 + 2];
        const float4* we = (const float4*)(Wij + (long)e * 384);
        const float4* xr = (const float4*)(g_x + (long)r * 384);
        const float4* vr = (const float4*)(v + (long)r * 384);

        float4 w0 = we[lane],      x0 = xr[lane];
        float4 w1 = we[32 + lane], x1 = xr[32 + lane];
        float4 w2 = we[64 + lane], x2 = xr[64 + lane];

        ds = f4fma4(w0, x0, ds);
        float4 m1 = f4mul(w1, x1);   // dv1 coeff
        float4 m2 = f4mul(w2, x2);   // dv2 coeff

        float4 vj0 = vr[lane], vj1 = vr[32 + lane], vj2 = vr[64 + lane];
        dv0 = f4fma(d0, m1, dv0); dv0 = f4fma4(m2, vj0, dv0);
        dv1 = f4fma(d1, m1, dv1); dv1 = f4fma4(m2, vj1, dv1);
        dv2 = f4fma(d2, m1, dv2); dv2 = f4fma4(m2, vj2, dv2);
    }

    float4 s4 = ((const float4*)(s + node * HDIM))[lane];
    ((float4*)(out_s + node * HDIM))[lane] = f4add(s4, f4clip(ds));

    const float4* vi = (const float4*)(v + (long)node * 384);
    float4* vo = (float4*)(out_v + (long)node * 384);
    vo[lane]      = f4add(vi[lane],      f4clip(dv0));
    vo[32 + lane] = f4add(vi[32 + lane], f4clip(dv1));
    vo[64 + lane] = f4add(vi[64 + lane], f4clip(dv2));
}

// ============================================================
// Kernel 3: intra-particle update, one warp per node, in-place on out_s/out_v
// ============================================================
__global__ void k_update(float* __restrict__ out_s, float* __restrict__ out_v,
                         const float* __restrict__ Wv,
                         const float* __restrict__ Wm1, const float* __restrict__ bm1,
                         const float* __restrict__ Wm2, const float* __restrict__ bm2) {
    int node = (blockIdx.x * blockDim.x + threadIdx.x) >> 5;
    int lane = threadIdx.x & 31;
    int wl   = threadIdx.x >> 5;
    __shared__ float small[8 * 768];  // per warp: ts(256) + v(384) + hidden(128)
    if (node >= N_NODES) return;

    float* ts  = small + wl * 768;   // [0:128)=s, [128:256)=v_norm
    float* vsm = ts + 256;           // 384
    float* hid = vsm + 384;          // 128

    float4 s4 = ((const float4*)(out_s + node * HDIM))[lane];
    ((float4*)ts)[lane] = s4;
    float4 vreg[3];
#pragma unroll
    for (int d = 0; d < 3; d++) {
        vreg[d] = ((const float4*)(out_v + (long)node * 384 + d * 128))[lane];
        ((float4*)vsm)[d * 32 + lane] = vreg[d];
    }
    __syncwarp();

    // v @ Wv -> v_l (cols 0:128), v_r (cols 128:256); lane owns cols lane*4..+3
    float4 vl[3], vr[3];
#pragma unroll
    for (int d = 0; d < 3; d++) { vl[d] = f4z(); vr[d] = f4z(); }
#pragma unroll 4
    for (int k = 0; k < 128; k++) {
        float4 wL = *(const float4*)(Wv + k * 256 + lane * 4);
        float4 wR = *(const float4*)(Wv + k * 256 + 128 + lane * 4);
        float v0 = vsm[k], v1 = vsm[128 + k], v2 = vsm[256 + k];
        vl[0] = f4fma(v0, wL, vl[0]); vr[0] = f4fma(v0, wR, vr[0]);
        vl[1] = f4fma(v1, wL, vl[1]); vr[1] = f4fma(v1, wR, vr[1]);
        vl[2] = f4fma(v2, wL, vl[2]); vr[2] = f4fma(v2, wR, vr[2]);
    }

    // v_norm = sqrt(sum_d v_r^2 + eps)
    float4 vn;
    vn.x = sqrtf(vr[0].x*vr[0].x + vr[1].x*vr[1].x + vr[2].x*vr[2].x + 1e-8f);
    vn.y = sqrtf(vr[0].y*vr[0].y + vr[1].y*vr[1].y + vr[2].y*vr[2].y + 1e-8f);
    vn.z = sqrtf(vr[0].z*vr[0].z + vr[1].z*vr[1].z + vr[2].z*vr[2].z + 1e-8f);
    vn.w = sqrtf(vr[0].w*vr[0].w + vr[1].w*vr[1].w + vr[2].w*vr[2].w + 1e-8f);
    ((float4*)ts)[32 + lane] = vn;
    __syncwarp();

    // hidden = silu(ts @ Wm1 + bm1)
    float4 h4 = f4z();
#pragma unroll 8
    for (int k = 0; k < 256; k++) {
        float tk = ts[k];
        float4 w = *(const float4*)(Wm1 + k * 128 + lane * 4);
        h4 = f4fma(tk, w, h4);
    }
    h4 = f4add(h4, ((const float4*)bm1)[lane]);
    h4 = f4silu(h4);
    ((float4*)hid)[lane] = h4;
    __syncwarp();

    // out = hidden @ Wm2 + bm2 -> [ds_u | dv_u | dsv]
    float4 o0 = f4z(), o1 = f4z(), o2 = f4z();
#pragma unroll 4
    for (int k = 0; k < 128; k++) {
        float hk = hid[k];
        o0 = f4fma(hk, *(const float4*)(Wm2 + k * 384 + lane * 4), o0);
        o1 = f4fma(hk, *(const float4*)(Wm2 + k * 384 + 128 + lane * 4), o1);
        o2 = f4fma(hk, *(const float4*)(Wm2 + k * 384 + 256 + lane * 4), o2);
    }
    o0 = f4add(o0, ((const float4*)(bm2))[lane]);
    o1 = f4add(o1, ((const float4*)(bm2 + 128))[lane]);
    o2 = f4add(o2, ((const float4*)(bm2 + 256))[lane]);

    // dot = sum_d v_r * v_l (per column)
    float4 dot;
    dot.x = vr[0].x*vl[0].x + vr[1].x*vl[1].x + vr[2].x*vl[2].x;
    dot.y = vr[0].y*vl[0].y + vr[1].y*vl[1].y + vr[2].y*vl[2].y;
    dot.z = vr[0].z*vl[0].z + vr[1].z*vl[1].z + vr[2].z*vl[2].z;
    dot.w = vr[0].w*vl[0].w + vr[1].w*vl[1].w + vr[2].w*vl[2].w;

    float4 dstot;
    dstot.x = clip100(o0.x + o2.x * dot.x);
    dstot.y = clip100(o0.y + o2.y * dot.y);
    dstot.z = clip100(o0.z + o2.z * dot.z);
    dstot.w = clip100(o0.w + o2.w * dot.w);
    ((float4*)(out_s + node * HDIM))[lane] = f4add(s4, dstot);

#pragma unroll
    for (int d = 0; d < 3; d++) {
        float4 dv = f4clip(f4mul(vl[d], o1));
        ((float4*)(out_v + (long)node * 384 + d * 128))[lane] = f4add(vreg[d], dv);
    }
}

// ============================================================
extern "C" void kernel_launch(void* const* d_in, const int* in_sizes, int n_in,
                              void* d_out, int out_size) {
    const float* s     = (const float*)d_in[0];
    const float* v     = (const float*)d_in[1];
    const float* dir   = (const float*)d_in[2];
    const float* Wij   = (const float*)d_in[3];
    const float* Wi1   = (const float*)d_in[4];
    const float* bi1   = (const float*)d_in[5];
    const float* Wi2   = (const float*)d_in[6];
    const float* bi2   = (const float*)d_in[7];
    const float* Wm1   = (const float*)d_in[8];
    const float* bm1   = (const float*)d_in[9];
    const float* Wm2   = (const float*)d_in[10];
    const float* bm2   = (const float*)d_in[11];
    const float* Wv    = (const float*)d_in[12];
    const int*   snd   = (const int*)d_in[13];
    const int*   rcv   = (const int*)d_in[14];

    float* out_s = (float*)d_out;                       // (N, 128)
    float* out_v = (float*)d_out + (long)N_NODES * HDIM; // (N, 3, 128)

    const int TPB = 256;
    int node_warp_blocks = (N_NODES * 32 + TPB - 1) / TPB;
    int node_blocks      = (N_NODES + TPB - 1) / TPB;
    int edge_blocks      = (N_EDGES + TPB - 1) / TPB;

    // node MLP (independent of CSR build -> can run first)
    k_node_mlp<<<node_warp_blocks, TPB>>>(s, Wi1, bi1, Wi2, bi2);

    // CSR by sender
    k_zero_cnt<<<node_blocks, TPB>>>();
    k_count<<<edge_blocks, TPB>>>(snd);
    k_scan<<<1, 1024>>>();
    k_fill<<<edge_blocks, TPB>>>(snd);

    // message + aggregate
    k_message<<<node_warp_blocks, TPB>>>(s, v, dir, Wij, rcv, out_s, out_v);

    // intra-particle update (in place)
    k_update<<<node_warp_blocks, TPB>>>(out_s, out_v, Wv, Wm1, bm1, Wm2, bm2);
}

// round 2
// speedup vs baseline: 1.7159x; 1.7159x over previous
#include <cuda_runtime.h>
#include <math.h>

#define N_NODES 25000
#define N_EDGES 400000
#define HDIM 128
typedef unsigned long long ULL;

// ---- device scratch (no allocations allowed) ----
__device__ float g_h [N_NODES * 128];
__device__ float g_x [N_NODES * 384];
__device__ float g_vw[N_NODES * 3 * 256];
__device__ float g_ts[N_NODES * 256];
__device__ float g_dot[N_NODES * 128];
__device__ float g_hm[N_NODES * 128];
__device__ float g_o [N_NODES * 384];
__device__ int   g_cnt[N_NODES];
__device__ int   g_off[N_NODES + 1];
__device__ int   g_cur[N_NODES];
__device__ int   g_eidx[N_EDGES];
__device__ int   g_bsum[32];
__device__ int   g_bpre[32];

__device__ __forceinline__ float silu_f(float x) { return x / (1.0f + __expf(-x)); }
__device__ __forceinline__ float clip100(float x) { return fminf(fmaxf(x, -100.0f), 100.0f); }

__device__ __forceinline__ ULL pack2(float x, float y) {
    ULL r; asm("mov.b64 %0, {%1,%2};" : "=l"(r) : "f"(x), "f"(y)); return r;
}
__device__ __forceinline__ void unpack2(ULL p, float& x, float& y) {
    asm("mov.b64 {%0,%1}, %2;" : "=f"(x), "=f"(y) : "l"(p));
}
__device__ __forceinline__ ULL fma2(ULL a, ULL b, ULL c) {
    ULL d; asm("fma.rn.f32x2 %0, %1, %2, %3;" : "=l"(d) : "l"(a), "l"(b), "l"(c)); return d;
}

__device__ __forceinline__ float4 f4z() { float4 r; r.x=r.y=r.z=r.w=0.f; return r; }
__device__ __forceinline__ float4 f4fma(float a, float4 b, float4 c) {
    c.x = fmaf(a, b.x, c.x); c.y = fmaf(a, b.y, c.y);
    c.z = fmaf(a, b.z, c.z); c.w = fmaf(a, b.w, c.w); return c;
}
__device__ __forceinline__ float4 f4mul(float4 a, float4 b) {
    float4 r; r.x=a.x*b.x; r.y=a.y*b.y; r.z=a.z*b.z; r.w=a.w*b.w; return r;
}
__device__ __forceinline__ float4 f4fma4(float4 a, float4 b, float4 c) {
    c.x = fmaf(a.x, b.x, c.x); c.y = fmaf(a.y, b.y, c.y);
    c.z = fmaf(a.z, b.z, c.z); c.w = fmaf(a.w, b.w, c.w); return c;
}
__device__ __forceinline__ float4 f4add(float4 a, float4 b) {
    float4 r; r.x=a.x+b.x; r.y=a.y+b.y; r.z=a.z+b.z; r.w=a.w+b.w; return r;
}
__device__ __forceinline__ float4 f4clip(float4 a) {
    float4 r; r.x=clip100(a.x); r.y=clip100(a.y); r.z=clip100(a.z); r.w=clip100(a.w); return r;
}

// ============================================================
// Tiled SGEMM with packed f32x2 FMAs.
// C[M,N] = A[M,K] @ B[K,N] (+bias) (+silu).  N % 128 == 0, K % 16 == 0.
// BM=BN=128, BK=16, 256 threads, 8x8 per thread (as 8x4 f32x2 pairs).
// EPI: 0 = none, 1 = +bias, 2 = silu(+bias)
// ============================================================
template<int EPI>
__global__ __launch_bounds__(256)
void k_gemm(const float* __restrict__ A, const float* __restrict__ B,
            const float* __restrict__ bias, float* __restrict__ C,
            int M, int N, int K)
{
    __shared__ float As[16][128];
    __shared__ float Bs[16][128];
    const int t  = threadIdx.x;
    const int m0 = blockIdx.x * 128;
    const int n0 = blockIdx.y * 128;
    const int tx = t & 15;        // 16 col-groups of 8
    const int ty = t >> 4;        // 16 row-groups of 8

    ULL acc[8][4];
#pragma unroll
    for (int i = 0; i < 8; i++)
#pragma unroll
        for (int j = 0; j < 4; j++) acc[i][j] = 0ULL;

    const int ar = t >> 2;            // 0..63
    const int ac = (t & 3) * 4;       // 0,4,8,12
    const int br = t >> 5;            // 0..7
    const int bc = (t & 31) * 4;      // 0..124

    for (int k0 = 0; k0 < K; k0 += 16) {
#pragma unroll
        for (int p = 0; p < 2; p++) {
            int row = m0 + ar + p * 64;
            float4 va = f4z();
            if (row < M) va = *(const float4*)(A + (long)row * K + k0 + ac);
            As[ac + 0][ar + p * 64] = va.x;
            As[ac + 1][ar + p * 64] = va.y;
            As[ac + 2][ar + p * 64] = va.z;
            As[ac + 3][ar + p * 64] = va.w;
        }
#pragma unroll
        for (int p = 0; p < 2; p++) {
            int kk = k0 + br + p * 8;
            *(float4*)&Bs[br + p * 8][bc] = *(const float4*)(B + (long)kk * N + n0 + bc);
        }
        __syncthreads();
#pragma unroll
        for (int k = 0; k < 16; k++) {
            float4 a0 = *(const float4*)&As[k][ty * 8];
            float4 a1 = *(const float4*)&As[k][ty * 8 + 4];
            ulonglong2 b0 = *(const ulonglong2*)&Bs[k][tx * 8];
            ulonglong2 b1 = *(const ulonglong2*)&Bs[k][tx * 8 + 4];
            ULL bp0 = b0.x, bp1 = b0.y, bp2 = b1.x, bp3 = b1.y;
            float av[8] = {a0.x, a0.y, a0.z, a0.w, a1.x, a1.y, a1.z, a1.w};
#pragma unroll
            for (int i = 0; i < 8; i++) {
                ULL a2 = pack2(av[i], av[i]);
                acc[i][0] = fma2(a2, bp0, acc[i][0]);
                acc[i][1] = fma2(a2, bp1, acc[i][1]);
                acc[i][2] = fma2(a2, bp2, acc[i][2]);
                acc[i][3] = fma2(a2, bp3, acc[i][3]);
            }
        }
        __syncthreads();
    }

    float bv[8];
    if (EPI > 0) {
        float4 bb0 = *(const float4*)(bias + n0 + tx * 8);
        float4 bb1 = *(const float4*)(bias + n0 + tx * 8 + 4);
        bv[0]=bb0.x; bv[1]=bb0.y; bv[2]=bb0.z; bv[3]=bb0.w;
        bv[4]=bb1.x; bv[5]=bb1.y; bv[6]=bb1.z; bv[7]=bb1.w;
    }
#pragma unroll
    for (int i = 0; i < 8; i++) {
        int row = m0 + ty * 8 + i;
        if (row < M) {
            float c[8];
#pragma unroll
            for (int j = 0; j < 4; j++) unpack2(acc[i][j], c[2*j], c[2*j+1]);
            if (EPI > 0) {
#pragma unroll
                for (int u = 0; u < 8; u++) c[u] += bv[u];
            }
            if (EPI == 2) {
#pragma unroll
                for (int u = 0; u < 8; u++) c[u] = silu_f(c[u]);
            }
            float4 o0; o0.x=c[0]; o0.y=c[1]; o0.z=c[2]; o0.w=c[3];
            float4 o1; o1.x=c[4]; o1.y=c[5]; o1.z=c[6]; o1.w=c[7];
            *(float4*)(C + (long)row * N + n0 + tx * 8)     = o0;
            *(float4*)(C + (long)row * N + n0 + tx * 8 + 4) = o1;
        }
    }
}

// ============================================================
// CSR build by sender (parallel 3-kernel scan)
// ============================================================
__global__ void k_zero_cnt() {
    int i = blockIdx.x * blockDim.x + threadIdx.x;
    if (i < N_NODES) g_cnt[i] = 0;
}
__global__ void k_count(const int* __restrict__ senders) {
    int e = blockIdx.x * blockDim.x + threadIdx.x;
    if (e < N_EDGES) atomicAdd(&g_cnt[senders[e]], 1);
}
__global__ void k_scanA() {
    __shared__ int sm[1024];
    int t = threadIdx.x;
    int i = blockIdx.x * 1024 + t;
    int v = (i < N_NODES) ? g_cnt[i] : 0;
    sm[t] = v;
    __syncthreads();
    for (int off = 1; off < 1024; off <<= 1) {
        int x = (t >= off) ? sm[t - off] : 0;
        __syncthreads();
        sm[t] += x;
        __syncthreads();
    }
    if (i < N_NODES) g_off[i] = sm[t] - v;   // block-local exclusive
    if (t == 1023) g_bsum[blockIdx.x] = sm[1023];
}
__global__ void k_scanB(int nblk) {
    int t = threadIdx.x;   // 32 threads
    int v = (t < nblk) ? g_bsum[t] : 0;
    int inc = v;
    for (int off = 1; off < 32; off <<= 1) {
        int x = __shfl_up_sync(0xffffffff, inc, off);
        if (t >= off) inc += x;
    }
    if (t < nblk) g_bpre[t] = inc - v;       // exclusive
    if (t == nblk - 1) g_off[N_NODES] = inc; // total = N_EDGES
}
__global__ void k_scanC() {
    int i = blockIdx.x * 1024 + threadIdx.x;
    if (i < N_NODES) {
        int o = g_off[i] + g_bpre[blockIdx.x];
        g_off[i] = o;
        g_cur[i] = o;
    }
}
__global__ void k_fill(const int* __restrict__ senders) {
    int e = blockIdx.x * blockDim.x + threadIdx.x;
    if (e < N_EDGES) {
        int p = atomicAdd(&g_cur[senders[e]], 1);
        g_eidx[p] = e;
    }
}

// ============================================================
// Message gather-reduce: one warp per node (sender)
// ============================================================
__global__ void k_message(const float* __restrict__ s, const float* __restrict__ v,
                          const float* __restrict__ dir_ij, const float* __restrict__ Wij,
                          const int* __restrict__ receivers,
                          float* __restrict__ out_s, float* __restrict__ out_v) {
    int node = (blockIdx.x * blockDim.x + threadIdx.x) >> 5;
    int lane = threadIdx.x & 31;
    if (node >= N_NODES) return;

    float4 ds  = f4z();
    float4 dv0 = f4z(), dv1 = f4z(), dv2 = f4z();

    int beg = g_off[node], end = g_off[node + 1];
    for (int i = beg; i < end; i++) {
        int e = g_eidx[i];
        int r = receivers[e];
        float d0 = dir_ij[e * 3 + 0];
        float d1 = dir_ij[e * 3 + 1];
        float d2 = dir_ij[e * 3 + 2];
        const float4* we = (const float4*)(Wij + (long)e * 384);
        const float4* xr = (const float4*)(g_x + (long)r * 384);
        const float4* vr = (const float4*)(v + (long)r * 384);

        float4 w0 = we[lane],      x0 = xr[lane];
        float4 w1 = we[32 + lane], x1 = xr[32 + lane];
        float4 w2 = we[64 + lane], x2 = xr[64 + lane];

        ds = f4fma4(w0, x0, ds);
        float4 m1 = f4mul(w1, x1);
        float4 m2 = f4mul(w2, x2);

        float4 vj0 = vr[lane], vj1 = vr[32 + lane], vj2 = vr[64 + lane];
        dv0 = f4fma(d0, m1, dv0); dv0 = f4fma4(m2, vj0, dv0);
        dv1 = f4fma(d1, m1, dv1); dv1 = f4fma4(m2, vj1, dv1);
        dv2 = f4fma(d2, m1, dv2); dv2 = f4fma4(m2, vj2, dv2);
    }

    float4 s4 = ((const float4*)(s + node * HDIM))[lane];
    ((float4*)(out_s + node * HDIM))[lane] = f4add(s4, f4clip(ds));

    const float4* vi = (const float4*)(v + (long)node * 384);
    float4* vo = (float4*)(out_v + (long)node * 384);
    vo[lane]      = f4add(vi[lane],      f4clip(dv0));
    vo[32 + lane] = f4add(vi[32 + lane], f4clip(dv1));
    vo[64 + lane] = f4add(vi[64 + lane], f4clip(dv2));
}

// ============================================================
// Build ts = [s | v_norm] and dot = sum_d vl*vr from g_vw
// one thread per (node, col)
// ============================================================
__global__ void k_ts(const float* __restrict__ out_s) {
    long idx = (long)blockIdx.x * blockDim.x + threadIdx.x;
    if (idx >= (long)N_NODES * 128) return;
    int n = (int)(idx >> 7);
    int c = (int)(idx & 127);
    const float* vw = g_vw + (long)n * 3 * 256;
    float vl0 = vw[c],           vr0 = vw[128 + c];
    float vl1 = vw[256 + c],     vr1 = vw[384 + c];
    float vl2 = vw[512 + c],     vr2 = vw[640 + c];
    float vn = sqrtf(vr0*vr0 + vr1*vr1 + vr2*vr2 + 1e-8f);
    g_ts[(long)n * 256 + c]       = out_s[(long)n * 128 + c];
    g_ts[(long)n * 256 + 128 + c] = vn;
    g_dot[idx] = vr0*vl0 + vr1*vl1 + vr2*vl2;
}

// ============================================================
// Final epilogue: s += clip(ds_u + dsv*dot), v += clip(vl * dv_u)
// ============================================================
__global__ void k_final(float* __restrict__ out_s, float* __restrict__ out_v) {
    long idx = (long)blockIdx.x * blockDim.x + threadIdx.x;
    if (idx >= (long)N_NODES * 128) return;
    int n = (int)(idx >> 7);
    int c = (int)(idx & 127);
    const float* O = g_o + (long)n * 384;
    float o0 = O[c], o1 = O[128 + c], o2 = O[256 + c];
    float dot = g_dot[idx];
    out_s[idx] += clip100(o0 + o2 * dot);
    const float* vw = g_vw + (long)n * 3 * 256;
    float* vv = out_v + (long)n * 384;
#pragma unroll
    for (int d = 0; d < 3; d++) {
        float vl = vw[d * 256 + c];
        vv[d * 128 + c] += clip100(vl * o1);
    }
}

// ============================================================
extern "C" void kernel_launch(void* const* d_in, const int* in_sizes, int n_in,
                              void* d_out, int out_size) {
    const float* s   = (const float*)d_in[0];
    const float* v   = (const float*)d_in[1];
    const float* dir = (const float*)d_in[2];
    const float* Wij = (const float*)d_in[3];
    const float* Wi1 = (const float*)d_in[4];
    const float* bi1 = (const float*)d_in[5];
    const float* Wi2 = (const float*)d_in[6];
    const float* bi2 = (const float*)d_in[7];
    const float* Wm1 = (const float*)d_in[8];
    const float* bm1 = (const float*)d_in[9];
    const float* Wm2 = (const float*)d_in[10];
    const float* bm2 = (const float*)d_in[11];
    const float* Wv  = (const float*)d_in[12];
    const int*   snd = (const int*)d_in[13];
    const int*   rcv = (const int*)d_in[14];

    float* out_s = (float*)d_out;
    float* out_v = (float*)d_out + (long)N_NODES * HDIM;

    float* p_h;  cudaGetSymbolAddress((void**)&p_h,  g_h);
    float* p_x;  cudaGetSymbolAddress((void**)&p_x,  g_x);
    float* p_vw; cudaGetSymbolAddress((void**)&p_vw, g_vw);
    float* p_ts; cudaGetSymbolAddress((void**)&p_ts, g_ts);
    float* p_hm; cudaGetSymbolAddress((void**)&p_hm, g_hm);
    float* p_o;  cudaGetSymbolAddress((void**)&p_o,  g_o);

    const int TPB = 256;
    int node_blocks = (N_NODES + TPB - 1) / TPB;
    int edge_blocks = (N_EDGES + TPB - 1) / TPB;
    int node_warp_blocks = (N_NODES * 32 + TPB - 1) / TPB;
    int nc_blocks = (int)(((long)N_NODES * 128 + TPB - 1) / TPB);
    const int MB = (N_NODES + 127) / 128;       // 196
    const int MB3 = (N_NODES * 3 + 127) / 128;  // 587
    const int SCAN_BLK = (N_NODES + 1023) / 1024; // 25

    // node MLP: h = silu(s@Wi1+b1); x = h@Wi2+b2
    k_gemm<2><<<dim3(MB, 1), 256>>>(s,   Wi1, bi1, p_h, N_NODES, 128, 128);
    k_gemm<1><<<dim3(MB, 3), 256>>>(p_h, Wi2, bi2, p_x, N_NODES, 384, 128);

    // CSR by sender
    k_zero_cnt<<<node_blocks, TPB>>>();
    k_count<<<edge_blocks, TPB>>>(snd);
    k_scanA<<<SCAN_BLK, 1024>>>();
    k_scanB<<<1, 32>>>(SCAN_BLK);
    k_scanC<<<SCAN_BLK, 1024>>>();
    k_fill<<<edge_blocks, TPB>>>(snd);

    // message + aggregate
    k_message<<<node_warp_blocks, TPB>>>(s, v, dir, Wij, rcv, out_s, out_v);

    // update: vw = v@Wv ; ts/dot ; hm = silu(ts@Wm1+b) ; O = hm@Wm2+b ; final
    k_gemm<0><<<dim3(MB3, 2), 256>>>(out_v, Wv, (const float*)0, p_vw, N_NODES * 3, 256, 128);
    k_ts<<<nc_blocks, TPB>>>(out_s);
    k_gemm<2><<<dim3(MB, 1), 256>>>(p_ts, Wm1, bm1, p_hm, N_NODES, 128, 256);
    k_gemm<1><<<dim3(MB, 3), 256>>>(p_hm, Wm2, bm2, p_o, N_NODES, 384, 128);
    k_final<<<nc_blocks, TPB>>>(out_s, out_v);
}